// round 6
// baseline (speedup 1.0000x reference)
#include <cuda_runtime.h>
#include <cstdint>
#include <cstdio>

#define T_SEQ 512
#define B_TOT 512
#define H_DIM 128
#define G3    384   // 3*H

// ---------------- scratch (no allocations allowed) ----------------
__device__ float g_gi[(size_t)B_TOT * T_SEQ * G3];     // 402 MB, reused for both layers
__device__ float g_h1[(size_t)B_TOT * T_SEQ * H_DIM];  // 134 MB

// ---------------- f32x2 helpers ----------------
__device__ __forceinline__ unsigned long long pack2(float lo, float hi) {
    unsigned long long r;
    asm("mov.b64 %0, {%1, %2};" : "=l"(r) : "f"(lo), "f"(hi));
    return r;
}
__device__ __forceinline__ void unpack2(unsigned long long v, float& lo, float& hi) {
    asm("mov.b64 {%0, %1}, %2;" : "=f"(lo), "=f"(hi) : "l"(v));
}
__device__ __forceinline__ unsigned long long ffma2(unsigned long long a,
                                                    unsigned long long b,
                                                    unsigned long long c) {
    unsigned long long d;
    asm("fma.rn.f32x2 %0, %1, %2, %3;" : "=l"(d) : "l"(a), "l"(b), "l"(c));
    return d;
}

__device__ __forceinline__ float sigf(float x) {
    return __fdividef(1.0f, 1.0f + __expf(-x));
}
__device__ __forceinline__ float tanhfast(float x) {
    const float e = __expf(-2.0f * x);
    return __fdividef(1.0f - e, 1.0f + e);
}

// ---------------------------------------------------------------------------
// Kernel A/C: gi[M,384] = X[M,K] @ W[384,K]^T + bias[384]
// Grid (M/32, 2). Block 384 threads = 12 warps. Warp w owns 16 columns
// (cb0 + 16w .. +16), lane = row (32 rows). Per 4-k chunk:
//   1 LDS.128 (X row, conflict-free) + 16 broadcast LDG.128 (W, 1 wf each,
//   L1-resident) -> 32 FFMA2.  Output transposed through smem -> STG.128.
// ---------------------------------------------------------------------------
template<int K>
__global__ __launch_bounds__(384, 2)
void gemm_ih(const float* __restrict__ X, const float* __restrict__ W,
             const float* __restrict__ bias, float* __restrict__ out)
{
    constexpr int XSTR = K + 4;           // row stride (16B aligned, conflict-free)
    __shared__ float xs[32 * XSTR];
    __shared__ float os[32 * 197];        // output transpose buffer (pad 197: cf)

    const int tid = threadIdx.x;
    const int w   = tid >> 5;
    const int l   = tid & 31;
    const int r0  = blockIdx.x * 32;
    const int cb0 = blockIdx.y * 192;
    const int cb  = cb0 + w * 16;

    // stage X tile (coalesced LDG.128 -> aligned STS.128)
    for (int i4 = tid; i4 < 32 * (K / 4); i4 += 384) {
        const int r  = i4 / (K / 4);
        const int kc = i4 - r * (K / 4);
        *(float4*)(xs + r * XSTR + 4 * kc) =
            *(const float4*)(X + (size_t)(r0 + r) * K + 4 * kc);
    }
    __syncthreads();

    unsigned long long acc[16];
#pragma unroll
    for (int c = 0; c < 16; c++) acc[c] = pack2(bias[cb + c], 0.0f);

    const float* xrow = xs + l * XSTR;
#pragma unroll 2
    for (int kc = 0; kc < K / 4; kc++) {
        const ulonglong2 xq = *(const ulonglong2*)(xrow + 4 * kc);
        // first 8 columns
#pragma unroll
        for (int c = 0; c < 8; c++) {
            const ulonglong2 wq =
                *(const ulonglong2*)(W + (size_t)(cb + c) * K + 4 * kc);
            acc[c] = ffma2(wq.x, xq.x, acc[c]);
            acc[c] = ffma2(wq.y, xq.y, acc[c]);
        }
        // second 8 columns
#pragma unroll
        for (int c = 8; c < 16; c++) {
            const ulonglong2 wq =
                *(const ulonglong2*)(W + (size_t)(cb + c) * K + 4 * kc);
            acc[c] = ffma2(wq.x, xq.x, acc[c]);
            acc[c] = ffma2(wq.y, xq.y, acc[c]);
        }
    }

    // horizontal add -> transpose buffer (pad 197 => conflict-free scalar STS)
#pragma unroll
    for (int c = 0; c < 16; c++) {
        float lo, hi;
        unpack2(acc[c], lo, hi);
        os[l * 197 + w * 16 + c] = lo + hi;
    }
    __syncthreads();

    // coalesced store: 32 rows x 192 cols
    for (int i4 = tid; i4 < 32 * 48; i4 += 384) {
        const int r  = i4 / 48;
        const int c4 = i4 - r * 48;
        const float* s = os + r * 197 + 4 * c4;
        float4 v = make_float4(s[0], s[1], s[2], s[3]);
        *(float4*)(out + (size_t)(r0 + r) * G3 + cb0 + 4 * c4) = v;
    }
}

// ---------------------------------------------------------------------------
// Kernel B/D: GRU recurrence. 128 blocks x 4 batches, 384 threads.
// Thread (j2 = tid%192, kh = tid/192) owns gate columns {j2, j2+192} over
// k-half [kh*64, kh*64+64). W for both columns in registers (128 regs).
// Per k2: 2 broadcast LDS.128 -> 8 FFMA2 (ratio 1:4).
// kh=0 writes gh_s (+bias), kh=1 writes ph_s; gates phase sums inline.
// 2 barriers per step.
// ---------------------------------------------------------------------------
template<bool LAYER1>
__global__ __launch_bounds__(384, 1)
void gru_recur(const float* __restrict__ Whh, const float* __restrict__ bhh,
               const float* __restrict__ gi, float* __restrict__ h1out,
               const float* __restrict__ Wfc, const float* __restrict__ bfc,
               float* __restrict__ out)
{
    __shared__ float h_s[64 * 8];        // [k2][b][2]
    __shared__ float gh_s[4 * 384];      // kh=0 partial (+ bias)
    __shared__ float ph_s[4 * 384];      // kh=1 partial
    __shared__ float gi_s[2 * 4 * 384];  // double-buffered

    const int tid = threadIdx.x;
    const int j2  = tid % 192;
    const int kh  = tid / 192;           // uniform per warp (192 = 6 warps)
    const int c0  = j2;
    const int c1  = j2 + 192;
    const int b0  = blockIdx.x * 4;

    // W rows for both columns, this k-half, packed as k-pair doubles
    unsigned long long w2a[32], w2b[32];
    {
        const ulonglong2* wp0 = (const ulonglong2*)(Whh + (size_t)c0 * H_DIM + kh * 64);
        const ulonglong2* wp1 = (const ulonglong2*)(Whh + (size_t)c1 * H_DIM + kh * 64);
#pragma unroll
        for (int q = 0; q < 16; q++) {
            ulonglong2 v0 = wp0[q];
            w2a[2 * q] = v0.x; w2a[2 * q + 1] = v0.y;
            ulonglong2 v1 = wp1[q];
            w2b[2 * q] = v1.x; w2b[2 * q + 1] = v1.y;
        }
    }
    const float bh0 = bhh[c0];
    const float bh1 = bhh[c1];

    for (int i = tid; i < 512; i += 384) h_s[i] = 0.0f;
    {
        // preload gi(t=0): each thread covers its j column for 4 batches.
        const int j = tid < 384 ? tid : 0;  // tid==j here (384 threads)
#pragma unroll
        for (int b = 0; b < 4; b++)
            gi_s[b * 384 + j] = gi[((size_t)(b0 + b) * T_SEQ) * G3 + j];
    }
    __syncthreads();

    const int k2base = kh * 32;

    for (int t = 0; t < T_SEQ; t++) {
        float* gin = gi_s + (t & 1) * 1536;
        float* gip = gi_s + ((t + 1) & 1) * 1536;

        // prefetch gi(t+1)
        float gv0 = 0.f, gv1 = 0.f, gv2 = 0.f, gv3 = 0.f;
        const bool pf = (t + 1 < T_SEQ);
        if (pf) {
            const float* gb = gi + ((size_t)b0 * T_SEQ + (t + 1)) * G3 + tid;
            gv0 = gb[0];
            gv1 = gb[(size_t)T_SEQ * G3];
            gv2 = gb[(size_t)2 * T_SEQ * G3];
            gv3 = gb[(size_t)3 * T_SEQ * G3];
        }

        // partial gh for 2 columns x 4 batches over this k-half
        unsigned long long a00 = 0, a01 = 0, a02 = 0, a03 = 0;
        unsigned long long a10 = 0, a11 = 0, a12 = 0, a13 = 0;
        const float* hp = h_s + k2base * 8;
#pragma unroll
        for (int q = 0; q < 32; q++) {
            const ulonglong2 h01 = *(const ulonglong2*)(hp + q * 8);
            const ulonglong2 h23 = *(const ulonglong2*)(hp + q * 8 + 4);
            const unsigned long long wd0 = w2a[q];
            const unsigned long long wd1 = w2b[q];
            a00 = ffma2(wd0, h01.x, a00);
            a01 = ffma2(wd0, h01.y, a01);
            a02 = ffma2(wd0, h23.x, a02);
            a03 = ffma2(wd0, h23.y, a03);
            a10 = ffma2(wd1, h01.x, a10);
            a11 = ffma2(wd1, h01.y, a11);
            a12 = ffma2(wd1, h23.x, a12);
            a13 = ffma2(wd1, h23.y, a13);
        }
        {
            float lo, hi;
            float* dst = kh ? ph_s : gh_s;
            const float add0 = kh ? 0.0f : bh0;
            const float add1 = kh ? 0.0f : bh1;
            unpack2(a00, lo, hi); dst[c0]           = add0 + lo + hi;
            unpack2(a01, lo, hi); dst[384 + c0]     = add0 + lo + hi;
            unpack2(a02, lo, hi); dst[2 * 384 + c0] = add0 + lo + hi;
            unpack2(a03, lo, hi); dst[3 * 384 + c0] = add0 + lo + hi;
            unpack2(a10, lo, hi); dst[c1]           = add1 + lo + hi;
            unpack2(a11, lo, hi); dst[384 + c1]     = add1 + lo + hi;
            unpack2(a12, lo, hi); dst[2 * 384 + c1] = add1 + lo + hi;
            unpack2(a13, lo, hi); dst[3 * 384 + c1] = add1 + lo + hi;
        }
        __syncthreads();

        // gates + state update (512 items over 384 threads)
        for (int i = tid; i < 512; i += 384) {
            const int b  = i >> 7;
            const int jh = i & 127;
            const float* gib = gin + b * 384;
            const float* ghb = gh_s + b * 384;
            const float* phb = ph_s + b * 384;
            const float hr = ghb[jh]       + phb[jh];
            const float hz = ghb[jh + 128] + phb[jh + 128];
            const float hn = ghb[jh + 256] + phb[jh + 256];
            const float r = sigf(gib[jh]       + hr);
            const float z = sigf(gib[jh + 128] + hz);
            const float n = tanhfast(gib[jh + 256] + r * hn);
            const int hidx = (jh >> 1) * 8 + 2 * b + (jh & 1);
            const float ho = h_s[hidx];
            const float hv = n + z * (ho - n);
            h_s[hidx] = hv;
            if (LAYER1)
                h1out[((size_t)(b0 + b) * T_SEQ + t) * H_DIM + jh] = hv;
        }
        if (pf) {
            gip[tid]           = gv0;
            gip[384 + tid]     = gv1;
            gip[2 * 384 + tid] = gv2;
            gip[3 * 384 + tid] = gv3;
        }
        __syncthreads();
    }

    if (!LAYER1) {
        // out[b] = h_T[b] . W_fc + b_fc
        if (tid < 128) {
            const int w = tid >> 5;
            const int l = tid & 31;
            float s = 0.0f;
#pragma unroll
            for (int q = 0; q < 4; q++) {
                const int jh = l + 32 * q;
                s += h_s[(jh >> 1) * 8 + 2 * w + (jh & 1)] * Wfc[jh];
            }
#pragma unroll
            for (int off = 16; off; off >>= 1)
                s += __shfl_down_sync(0xffffffffu, s, off);
            if (l == 0) out[b0 + w] = s + bfc[0];
        }
    }
}

// ---------------------------------------------------------------------------
extern "C" void kernel_launch(void* const* d_in, const int* in_sizes, int n_in,
                              void* d_out, int out_size)
{
    const float* x     = (const float*)d_in[0];
    const float* W_ih0 = (const float*)d_in[1];
    const float* W_hh0 = (const float*)d_in[2];
    const float* b_ih0 = (const float*)d_in[3];
    const float* b_hh0 = (const float*)d_in[4];
    const float* W_ih1 = (const float*)d_in[5];
    const float* W_hh1 = (const float*)d_in[6];
    const float* b_ih1 = (const float*)d_in[7];
    const float* b_hh1 = (const float*)d_in[8];
    const float* W_fc  = (const float*)d_in[9];
    const float* b_fc  = (const float*)d_in[10];
    float* out = (float*)d_out;

    void *gi_p = nullptr, *h1_p = nullptr;
    cudaGetSymbolAddress(&gi_p, g_gi);
    cudaGetSymbolAddress(&h1_p, g_h1);
    float* gi = (float*)gi_p;
    float* h1 = (float*)h1_p;

    const int M = B_TOT * T_SEQ;  // 262144
    dim3 ggrid(M / 32, 2);

    // layer 1: input GEMM + recurrence (writes h1)
    gemm_ih<64><<<ggrid, 384>>>(x, W_ih0, b_ih0, gi);
    gru_recur<true><<<128, 384>>>(W_hh0, b_hh0, gi, h1,
                                  nullptr, nullptr, nullptr);
    // layer 2: input GEMM (from h1) + recurrence (fused FC)
    gemm_ih<128><<<ggrid, 384>>>(h1, W_ih1, b_ih1, gi);
    gru_recur<false><<<128, 384>>>(W_hh1, b_hh1, gi, nullptr,
                                   W_fc, b_fc, out);
}

// round 14
// speedup vs baseline: 1.0493x; 1.0493x over previous
#include <cuda_runtime.h>
#include <cuda_bf16.h>
#include <cstdint>

#define T_SEQ 512
#define B_TOT 512
#define H_DIM 128
#define G3    384   // 3*H
#define M_TOT (B_TOT * T_SEQ)   // 262144

// ---------------- scratch (no allocations allowed) ----------------
__device__ float        g_gi[(size_t)M_TOT * G3];        // 402 MB, reused both layers
__device__ __nv_bfloat16 g_xhi[(size_t)M_TOT * 64];
__device__ __nv_bfloat16 g_xlo[(size_t)M_TOT * 64];
__device__ __nv_bfloat16 g_h1hi[(size_t)M_TOT * H_DIM];
__device__ __nv_bfloat16 g_h1lo[(size_t)M_TOT * H_DIM];
__device__ __nv_bfloat16 g_w0hi[G3 * 64],  g_w0lo[G3 * 64];
__device__ __nv_bfloat16 g_w1hi[G3 * 128], g_w1lo[G3 * 128];

// ---------------- f32x2 helpers (recurrence) ----------------
__device__ __forceinline__ unsigned long long pack2(float lo, float hi) {
    unsigned long long r;
    asm("mov.b64 %0, {%1, %2};" : "=l"(r) : "f"(lo), "f"(hi));
    return r;
}
__device__ __forceinline__ void unpack2(unsigned long long v, float& lo, float& hi) {
    asm("mov.b64 {%0, %1}, %2;" : "=f"(lo), "=f"(hi) : "l"(v));
}
__device__ __forceinline__ unsigned long long ffma2(unsigned long long a,
                                                    unsigned long long b,
                                                    unsigned long long c) {
    unsigned long long d;
    asm("fma.rn.f32x2 %0, %1, %2, %3;" : "=l"(d) : "l"(a), "l"(b), "l"(c));
    return d;
}
__device__ __forceinline__ float sigf(float x) {
    return __fdividef(1.0f, 1.0f + __expf(-x));
}
__device__ __forceinline__ float tanhfast(float x) {
    const float e = __expf(-2.0f * x);
    return __fdividef(1.0f - e, 1.0f + e);
}

// ---------------- warp-level bf16 MMA (arch-generic, works on sm_103) -------
__device__ __forceinline__ void mma16816(float* c, const uint32_t* a,
                                         uint32_t b0, uint32_t b1) {
    asm volatile(
        "mma.sync.aligned.m16n8k16.row.col.f32.bf16.bf16.f32 "
        "{%0,%1,%2,%3}, {%4,%5,%6,%7}, {%8,%9}, {%0,%1,%2,%3};"
        : "+f"(c[0]), "+f"(c[1]), "+f"(c[2]), "+f"(c[3])
        : "r"(a[0]), "r"(a[1]), "r"(a[2]), "r"(a[3]), "r"(b0), "r"(b1));
}

// ---------------------------------------------------------------------------
// split: fp32 -> (bf16 hi, bf16 lo)
// ---------------------------------------------------------------------------
__global__ void split_hilo(const float* __restrict__ src,
                           __nv_bfloat16* __restrict__ hi,
                           __nv_bfloat16* __restrict__ lo, int n)
{
    int i = blockIdx.x * blockDim.x + threadIdx.x;
    const int stride = gridDim.x * blockDim.x;
    for (; i < n; i += stride) {
        const float v = src[i];
        const __nv_bfloat16 h = __float2bfloat16(v);
        hi[i] = h;
        lo[i] = __float2bfloat16(v - __bfloat162float(h));
    }
}

// ---------------------------------------------------------------------------
// gemm_mma: gi[M,384] = Xhi@Whi^T + Xhi@Wlo^T + Xlo@Whi^T + bias (fp32 accum)
// Grid (M/128, 3). CTA tile 128 rows x 128 gate-cols, 256 threads = 8 warps
// (warp grid 4x2 -> warp tile 32x64 = 2x8 m16n8k16 fragments, 64 accum regs).
// A/B staged in smem, row stride K0+8 bf16 (STR/2 === 4 mod 32 -> every
// fragment LDS.32 is 32-bank conflict-free). 3 hi/lo terms accumulate into
// the same regs; bias added in the smem-transpose epilogue -> STG.128.
// ---------------------------------------------------------------------------
#define GEMM_SMEM 70656

template<int K0>
__global__ __launch_bounds__(256, 1)
void gemm_mma(const __nv_bfloat16* __restrict__ Ahi, const __nv_bfloat16* __restrict__ Alo,
              const __nv_bfloat16* __restrict__ Whi, const __nv_bfloat16* __restrict__ Wlo,
              const float* __restrict__ bias, float* __restrict__ out)
{
    constexpr int STR = K0 + 8;          // bf16 units; STR/2 % 32 == 4
    extern __shared__ char smem[];
    __nv_bfloat16* As = (__nv_bfloat16*)smem;               // [128][STR]
    __nv_bfloat16* Bs = As + 128 * STR;                     // [128][STR]
    float* os = (float*)smem;                               // epilogue [128][132]

    const int tid  = threadIdx.x;
    const int wid  = tid >> 5;
    const int lane = tid & 31;
    const int gid  = lane >> 2;          // 0..7
    const int tig  = lane & 3;           // 0..3
    const int wm   = wid & 3;            // 0..3  (32 rows each)
    const int wn   = wid >> 2;           // 0..1  (64 cols each)
    const int m0   = blockIdx.x * 128;
    const int n0   = blockIdx.y * 128;

    float c[2][8][4];
#pragma unroll
    for (int i = 0; i < 2; i++)
#pragma unroll
        for (int j = 0; j < 8; j++)
#pragma unroll
            for (int q = 0; q < 4; q++) c[i][j][q] = 0.0f;

    constexpr int C8 = K0 / 8;           // float4 chunks per row

#pragma unroll 1
    for (int term = 0; term < 3; term++) {
        const __nv_bfloat16* asrc = (term < 2) ? Ahi : Alo;
        const __nv_bfloat16* bsrc = (term == 1) ? Wlo : Whi;

        __syncthreads();   // protect smem reuse across terms / epilogue
        // stage A: 128 rows x K0 (coalesced float4 = 8 bf16)
        for (int i = tid; i < 128 * C8; i += 256) {
            const int r  = i / C8;
            const int c8 = i - r * C8;
            *(float4*)(As + r * STR + c8 * 8) =
                *(const float4*)(asrc + (size_t)(m0 + r) * K0 + c8 * 8);
        }
        // stage B: 128 gate rows x K0
        for (int i = tid; i < 128 * C8; i += 256) {
            const int r  = i / C8;
            const int c8 = i - r * C8;
            *(float4*)(Bs + r * STR + c8 * 8) =
                *(const float4*)(bsrc + (size_t)(n0 + r) * K0 + c8 * 8);
        }
        __syncthreads();

#pragma unroll
        for (int kc = 0; kc < K0 / 16; kc++) {
            const int kb = kc * 16;
            uint32_t a[2][4];
#pragma unroll
            for (int i = 0; i < 2; i++) {
                const int rb = wm * 32 + i * 16;
                const __nv_bfloat16* ap = As + (size_t)(rb + gid) * STR + kb + 2 * tig;
                a[i][0] = *(const uint32_t*)(ap);
                a[i][1] = *(const uint32_t*)(ap + 8 * STR);
                a[i][2] = *(const uint32_t*)(ap + 8);
                a[i][3] = *(const uint32_t*)(ap + 8 * STR + 8);
            }
#pragma unroll
            for (int j = 0; j < 8; j++) {
                const __nv_bfloat16* bp =
                    Bs + (size_t)(wn * 64 + j * 8 + gid) * STR + kb + 2 * tig;
                const uint32_t b0 = *(const uint32_t*)(bp);
                const uint32_t b1 = *(const uint32_t*)(bp + 8);
                mma16816(c[0][j], a[0], b0, b1);
                mma16816(c[1][j], a[1], b0, b1);
            }
        }
    }
    __syncthreads();

    // epilogue: regs -> os[128][132] (+bias) -> coalesced STG.128
#pragma unroll
    for (int i = 0; i < 2; i++) {
#pragma unroll
        for (int j = 0; j < 8; j++) {
            const int r  = wm * 32 + i * 16 + gid;
            const int cb = wn * 64 + j * 8 + 2 * tig;
            const float2 bb = *(const float2*)(bias + n0 + cb);
            *(float2*)(os + r * 132 + cb) =
                make_float2(c[i][j][0] + bb.x, c[i][j][1] + bb.y);
            *(float2*)(os + (r + 8) * 132 + cb) =
                make_float2(c[i][j][2] + bb.x, c[i][j][3] + bb.y);
        }
    }
    __syncthreads();
    for (int i = tid; i < 128 * 32; i += 256) {
        const int r  = i >> 5;
        const int c4 = i & 31;
        *(float4*)(out + (size_t)(m0 + r) * G3 + n0 + 4 * c4) =
            *(const float4*)(os + r * 132 + 4 * c4);
    }
}

// ---------------------------------------------------------------------------
// GRU recurrence (R6 structure, calibrated near its RF-banking floor).
// 128 blocks x 4 batches, 384 threads. Layer 1 emits h1 as bf16 hi/lo.
// ---------------------------------------------------------------------------
template<bool LAYER1>
__global__ __launch_bounds__(384, 1)
void gru_recur(const float* __restrict__ Whh, const float* __restrict__ bhh,
               const float* __restrict__ gi,
               __nv_bfloat16* __restrict__ h1hi, __nv_bfloat16* __restrict__ h1lo,
               const float* __restrict__ Wfc, const float* __restrict__ bfc,
               float* __restrict__ out)
{
    __shared__ float h_s[64 * 8];        // [k2][b][2]
    __shared__ float gh_s[4 * 384];      // kh=0 partial (+ bias)
    __shared__ float ph_s[4 * 384];      // kh=1 partial
    __shared__ float gi_s[2 * 4 * 384];  // double-buffered

    const int tid = threadIdx.x;
    const int j2  = tid % 192;
    const int kh  = tid / 192;           // uniform per warp
    const int c0  = j2;
    const int c1  = j2 + 192;
    const int b0  = blockIdx.x * 4;

    unsigned long long w2a[32], w2b[32];
    {
        const ulonglong2* wp0 = (const ulonglong2*)(Whh + (size_t)c0 * H_DIM + kh * 64);
        const ulonglong2* wp1 = (const ulonglong2*)(Whh + (size_t)c1 * H_DIM + kh * 64);
#pragma unroll
        for (int q = 0; q < 16; q++) {
            ulonglong2 v0 = wp0[q];
            w2a[2 * q] = v0.x; w2a[2 * q + 1] = v0.y;
            ulonglong2 v1 = wp1[q];
            w2b[2 * q] = v1.x; w2b[2 * q + 1] = v1.y;
        }
    }
    const float bh0 = bhh[c0];
    const float bh1 = bhh[c1];

    for (int i = tid; i < 512; i += 384) h_s[i] = 0.0f;
#pragma unroll
    for (int b = 0; b < 4; b++)
        gi_s[b * 384 + tid] = gi[((size_t)(b0 + b) * T_SEQ) * G3 + tid];
    __syncthreads();

    const int k2base = kh * 32;

    for (int t = 0; t < T_SEQ; t++) {
        float* gin = gi_s + (t & 1) * 1536;
        float* gip = gi_s + ((t + 1) & 1) * 1536;

        float gv0 = 0.f, gv1 = 0.f, gv2 = 0.f, gv3 = 0.f;
        const bool pf = (t + 1 < T_SEQ);
        if (pf) {
            const float* gb = gi + ((size_t)b0 * T_SEQ + (t + 1)) * G3 + tid;
            gv0 = gb[0];
            gv1 = gb[(size_t)T_SEQ * G3];
            gv2 = gb[(size_t)2 * T_SEQ * G3];
            gv3 = gb[(size_t)3 * T_SEQ * G3];
        }

        unsigned long long a00 = 0, a01 = 0, a02 = 0, a03 = 0;
        unsigned long long a10 = 0, a11 = 0, a12 = 0, a13 = 0;
        const float* hp = h_s + k2base * 8;
#pragma unroll
        for (int q = 0; q < 32; q++) {
            const ulonglong2 h01 = *(const ulonglong2*)(hp + q * 8);
            const ulonglong2 h23 = *(const ulonglong2*)(hp + q * 8 + 4);
            const unsigned long long wd0 = w2a[q];
            const unsigned long long wd1 = w2b[q];
            a00 = ffma2(wd0, h01.x, a00);
            a01 = ffma2(wd0, h01.y, a01);
            a02 = ffma2(wd0, h23.x, a02);
            a03 = ffma2(wd0, h23.y, a03);
            a10 = ffma2(wd1, h01.x, a10);
            a11 = ffma2(wd1, h01.y, a11);
            a12 = ffma2(wd1, h23.x, a12);
            a13 = ffma2(wd1, h23.y, a13);
        }
        {
            float lo, hi;
            float* dst = kh ? ph_s : gh_s;
            const float add0 = kh ? 0.0f : bh0;
            const float add1 = kh ? 0.0f : bh1;
            unpack2(a00, lo, hi); dst[c0]           = add0 + lo + hi;
            unpack2(a01, lo, hi); dst[384 + c0]     = add0 + lo + hi;
            unpack2(a02, lo, hi); dst[2 * 384 + c0] = add0 + lo + hi;
            unpack2(a03, lo, hi); dst[3 * 384 + c0] = add0 + lo + hi;
            unpack2(a10, lo, hi); dst[c1]           = add1 + lo + hi;
            unpack2(a11, lo, hi); dst[384 + c1]     = add1 + lo + hi;
            unpack2(a12, lo, hi); dst[2 * 384 + c1] = add1 + lo + hi;
            unpack2(a13, lo, hi); dst[3 * 384 + c1] = add1 + lo + hi;
        }
        __syncthreads();

        for (int i = tid; i < 512; i += 384) {
            const int b  = i >> 7;
            const int jh = i & 127;
            const float* gib = gin + b * 384;
            const float* ghb = gh_s + b * 384;
            const float* phb = ph_s + b * 384;
            const float hr = ghb[jh]       + phb[jh];
            const float hz = ghb[jh + 128] + phb[jh + 128];
            const float hn = ghb[jh + 256] + phb[jh + 256];
            const float r = sigf(gib[jh]       + hr);
            const float z = sigf(gib[jh + 128] + hz);
            const float n = tanhfast(gib[jh + 256] + r * hn);
            const int hidx = (jh >> 1) * 8 + 2 * b + (jh & 1);
            const float ho = h_s[hidx];
            const float hv = n + z * (ho - n);
            h_s[hidx] = hv;
            if (LAYER1) {
                const size_t oidx = ((size_t)(b0 + b) * T_SEQ + t) * H_DIM + jh;
                const __nv_bfloat16 hh = __float2bfloat16(hv);
                h1hi[oidx] = hh;
                h1lo[oidx] = __float2bfloat16(hv - __bfloat162float(hh));
            }
        }
        if (pf) {
            gip[tid]           = gv0;
            gip[384 + tid]     = gv1;
            gip[2 * 384 + tid] = gv2;
            gip[3 * 384 + tid] = gv3;
        }
        __syncthreads();
    }

    if (!LAYER1) {
        if (tid < 128) {
            const int w = tid >> 5;
            const int l = tid & 31;
            float s = 0.0f;
#pragma unroll
            for (int q = 0; q < 4; q++) {
                const int jh = l + 32 * q;
                s += h_s[(jh >> 1) * 8 + 2 * w + (jh & 1)] * Wfc[jh];
            }
#pragma unroll
            for (int off = 16; off; off >>= 1)
                s += __shfl_down_sync(0xffffffffu, s, off);
            if (l == 0) out[b0 + w] = s + bfc[0];
        }
    }
}

// ---------------------------------------------------------------------------
extern "C" void kernel_launch(void* const* d_in, const int* in_sizes, int n_in,
                              void* d_out, int out_size)
{
    const float* x     = (const float*)d_in[0];
    const float* W_ih0 = (const float*)d_in[1];
    const float* W_hh0 = (const float*)d_in[2];
    const float* b_ih0 = (const float*)d_in[3];
    const float* b_hh0 = (const float*)d_in[4];
    const float* W_ih1 = (const float*)d_in[5];
    const float* W_hh1 = (const float*)d_in[6];
    const float* b_ih1 = (const float*)d_in[7];
    const float* b_hh1 = (const float*)d_in[8];
    const float* W_fc  = (const float*)d_in[9];
    const float* b_fc  = (const float*)d_in[10];
    float* out = (float*)d_out;

    void *p;
    cudaGetSymbolAddress(&p, g_gi);   float* gi = (float*)p;
    cudaGetSymbolAddress(&p, g_xhi);  __nv_bfloat16* xhi = (__nv_bfloat16*)p;
    cudaGetSymbolAddress(&p, g_xlo);  __nv_bfloat16* xlo = (__nv_bfloat16*)p;
    cudaGetSymbolAddress(&p, g_h1hi); __nv_bfloat16* h1hi = (__nv_bfloat16*)p;
    cudaGetSymbolAddress(&p, g_h1lo); __nv_bfloat16* h1lo = (__nv_bfloat16*)p;
    cudaGetSymbolAddress(&p, g_w0hi); __nv_bfloat16* w0hi = (__nv_bfloat16*)p;
    cudaGetSymbolAddress(&p, g_w0lo); __nv_bfloat16* w0lo = (__nv_bfloat16*)p;
    cudaGetSymbolAddress(&p, g_w1hi); __nv_bfloat16* w1hi = (__nv_bfloat16*)p;
    cudaGetSymbolAddress(&p, g_w1lo); __nv_bfloat16* w1lo = (__nv_bfloat16*)p;

    cudaFuncSetAttribute(gemm_mma<64>,  cudaFuncAttributeMaxDynamicSharedMemorySize, GEMM_SMEM);
    cudaFuncSetAttribute(gemm_mma<128>, cudaFuncAttributeMaxDynamicSharedMemorySize, GEMM_SMEM);

    // splits (x is 16.8M elems; W splits tiny)
    split_hilo<<<2048, 256>>>(x, xhi, xlo, M_TOT * 64);
    split_hilo<<<48, 256>>>(W_ih0, w0hi, w0lo, G3 * 64);
    split_hilo<<<96, 256>>>(W_ih1, w1hi, w1lo, G3 * 128);

    dim3 ggrid(M_TOT / 128, 3);
    // layer 1
    gemm_mma<64><<<ggrid, 256, GEMM_SMEM>>>(xhi, xlo, w0hi, w0lo, b_ih0, gi);
    gru_recur<true><<<128, 384>>>(W_hh0, b_hh0, gi, h1hi, h1lo,
                                  nullptr, nullptr, nullptr);
    // layer 2
    gemm_mma<128><<<ggrid, 256, GEMM_SMEM>>>(h1hi, h1lo, w1hi, w1lo, b_ih1, gi);
    gru_recur<false><<<128, 384>>>(W_hh1, b_hh1, gi, nullptr, nullptr,
                                   W_fc, b_fc, out);
}

// round 15
// speedup vs baseline: 1.8350x; 1.7488x over previous
#include <cuda_runtime.h>
#include <cuda_bf16.h>
#include <cstdint>

#define T_SEQ 512
#define B_TOT 512
#define H_DIM 128
#define G3    384   // 3*H
#define M_TOT (B_TOT * T_SEQ)   // 262144

// ---------------- scratch (no allocations allowed) ----------------
__device__ float        g_gi[(size_t)M_TOT * G3];        // 402 MB, reused both layers
__device__ __nv_bfloat16 g_xhi[(size_t)M_TOT * 64];
__device__ __nv_bfloat16 g_xlo[(size_t)M_TOT * 64];
__device__ __nv_bfloat16 g_h1hi[(size_t)M_TOT * H_DIM];
__device__ __nv_bfloat16 g_h1lo[(size_t)M_TOT * H_DIM];
__device__ __nv_bfloat16 g_w0hi[G3 * 64],  g_w0lo[G3 * 64];
__device__ __nv_bfloat16 g_w1hi[G3 * 128], g_w1lo[G3 * 128];

// ---------------- f32x2 helpers (recurrence) ----------------
__device__ __forceinline__ unsigned long long pack2(float lo, float hi) {
    unsigned long long r;
    asm("mov.b64 %0, {%1, %2};" : "=l"(r) : "f"(lo), "f"(hi));
    return r;
}
__device__ __forceinline__ void unpack2(unsigned long long v, float& lo, float& hi) {
    asm("mov.b64 {%0, %1}, %2;" : "=f"(lo), "=f"(hi) : "l"(v));
}
__device__ __forceinline__ unsigned long long ffma2(unsigned long long a,
                                                    unsigned long long b,
                                                    unsigned long long c) {
    unsigned long long d;
    asm("fma.rn.f32x2 %0, %1, %2, %3;" : "=l"(d) : "l"(a), "l"(b), "l"(c));
    return d;
}
__device__ __forceinline__ float sigf(float x) {
    return __fdividef(1.0f, 1.0f + __expf(-x));
}
__device__ __forceinline__ float tanhfast(float x) {
    const float e = __expf(-2.0f * x);
    return __fdividef(1.0f - e, 1.0f + e);
}

// ---------------- warp-level bf16 MMA + cp.async (arch-generic) -------------
__device__ __forceinline__ void mma16816(float* c, const uint32_t* a,
                                         uint32_t b0, uint32_t b1) {
    asm volatile(
        "mma.sync.aligned.m16n8k16.row.col.f32.bf16.bf16.f32 "
        "{%0,%1,%2,%3}, {%4,%5,%6,%7}, {%8,%9}, {%0,%1,%2,%3};"
        : "+f"(c[0]), "+f"(c[1]), "+f"(c[2]), "+f"(c[3])
        : "r"(a[0]), "r"(a[1]), "r"(a[2]), "r"(a[3]), "r"(b0), "r"(b1));
}
__device__ __forceinline__ uint32_t smem_u32(const void* p) {
    uint32_t a;
    asm("{ .reg .u64 t; cvta.to.shared.u64 t, %1; cvt.u32.u64 %0, t; }"
        : "=r"(a) : "l"(p));
    return a;
}
__device__ __forceinline__ void cp16(uint32_t s, const void* g) {
    asm volatile("cp.async.ca.shared.global [%0], [%1], 16;" :: "r"(s), "l"(g));
}
#define CP_COMMIT() asm volatile("cp.async.commit_group;" ::: "memory")
#define CP_WAIT1()  asm volatile("cp.async.wait_group 1;"  ::: "memory")
#define CP_WAIT0()  asm volatile("cp.async.wait_group 0;"  ::: "memory")

// ---------------------------------------------------------------------------
// split: fp32 -> (bf16 hi, bf16 lo)
// ---------------------------------------------------------------------------
__global__ void split_hilo(const float* __restrict__ src,
                           __nv_bfloat16* __restrict__ hi,
                           __nv_bfloat16* __restrict__ lo, int n)
{
    int i = blockIdx.x * blockDim.x + threadIdx.x;
    const int stride = gridDim.x * blockDim.x;
    for (; i < n; i += stride) {
        const float v = src[i];
        const __nv_bfloat16 h = __float2bfloat16(v);
        hi[i] = h;
        lo[i] = __float2bfloat16(v - __bfloat162float(h));
    }
}

// ---------------------------------------------------------------------------
// gemm_mma: gi[M,384] = Xhi@Whi^T + Xhi@Wlo^T + Xlo@Whi^T + bias (fp32 accum)
// Grid (M/128, 3). CTA 128x128 tile, 256 threads = 8 warps (4x2; warp tile
// 32x64 = 2x8 m16n8k16 frags). The 3-term hi/lo GEMM is a pipeline of
// NC = 3*K0/64 K-chunks of 64: chunk c+1 is cp.async-prefetched into the
// alternate smem buffer while MMAs consume chunk c (2 barriers/chunk).
// Chunk row stride 72 bf16 (36 words === 4 mod 32 -> conflict-free frag LDS).
// __launch_bounds__(256,2): regs<=128 -> 2 CTAs/SM for latency hiding.
// ---------------------------------------------------------------------------
#define STRC      72
#define CHUNK_B   (128 * STRC * 2)           // A or B half: 18432 B
#define BUF_B     (2 * CHUNK_B)              // one (A,B) buffer: 36864 B
#define GEMM_SMEM (2 * BUF_B)                // double-buffered: 73728 B

template<int K0>
__global__ __launch_bounds__(256, 2)
void gemm_mma(const __nv_bfloat16* __restrict__ Ahi, const __nv_bfloat16* __restrict__ Alo,
              const __nv_bfloat16* __restrict__ Whi, const __nv_bfloat16* __restrict__ Wlo,
              const float* __restrict__ bias, float* __restrict__ out)
{
    extern __shared__ char smem[];
    const uint32_t sbase = smem_u32(smem);
    float* os = (float*)smem;                // epilogue [128][132] (67.6KB <= 73.7KB)

    const int tid  = threadIdx.x;
    const int wid  = tid >> 5;
    const int lane = tid & 31;
    const int gid  = lane >> 2;              // 0..7
    const int tig  = lane & 3;               // 0..3
    const int wm   = wid & 3;                // 0..3  (32 rows each)
    const int wn   = wid >> 2;               // 0..1  (64 cols each)
    const int m0   = blockIdx.x * 128;
    const int n0   = blockIdx.y * 128;

    constexpr int NCK = K0 / 64;
    constexpr int NC  = 3 * NCK;

    float c[2][8][4];
#pragma unroll
    for (int i = 0; i < 2; i++)
#pragma unroll
        for (int j = 0; j < 8; j++)
#pragma unroll
            for (int q = 0; q < 4; q++) c[i][j][q] = 0.0f;

    // stage chunk cc into buffer b (issue only; no commit)
    auto stage = [&](int cc, int b) {
        const int term = cc / NCK;
        const int kq   = cc - term * NCK;
        const int koff = kq * 64;
        const __nv_bfloat16* asrc = (term < 2) ? Ahi : Alo;
        const __nv_bfloat16* bsrc = (term == 1) ? Wlo : Whi;
        const uint32_t ab = sbase + b * BUF_B;
        const uint32_t bb = ab + CHUNK_B;
#pragma unroll
        for (int it = 0; it < 4; it++) {
            const int i  = tid + it * 256;   // 0..1023
            const int r  = i >> 3;
            const int c8 = i & 7;
            cp16(ab + (r * STRC + c8 * 8) * 2,
                 asrc + (size_t)(m0 + r) * K0 + koff + c8 * 8);
            cp16(bb + (r * STRC + c8 * 8) * 2,
                 bsrc + (size_t)(n0 + r) * K0 + koff + c8 * 8);
        }
    };

    stage(0, 0);
    CP_COMMIT();

#pragma unroll 1
    for (int cc = 0; cc < NC; cc++) {
        if (cc + 1 < NC) {
            stage(cc + 1, (cc + 1) & 1);
            CP_COMMIT();
            CP_WAIT1();
        } else {
            CP_WAIT0();
        }
        __syncthreads();

        const __nv_bfloat16* Ab = (const __nv_bfloat16*)(smem + (cc & 1) * BUF_B);
        const __nv_bfloat16* Bb = (const __nv_bfloat16*)(smem + (cc & 1) * BUF_B + CHUNK_B);

#pragma unroll
        for (int kc = 0; kc < 4; kc++) {
            const int kb = kc * 16;
            uint32_t a[2][4];
#pragma unroll
            for (int i = 0; i < 2; i++) {
                const int rb = wm * 32 + i * 16;
                const __nv_bfloat16* ap = Ab + (size_t)(rb + gid) * STRC + kb + 2 * tig;
                a[i][0] = *(const uint32_t*)(ap);
                a[i][1] = *(const uint32_t*)(ap + 8 * STRC);
                a[i][2] = *(const uint32_t*)(ap + 8);
                a[i][3] = *(const uint32_t*)(ap + 8 * STRC + 8);
            }
#pragma unroll
            for (int j = 0; j < 8; j++) {
                const __nv_bfloat16* bp =
                    Bb + (size_t)(wn * 64 + j * 8 + gid) * STRC + kb + 2 * tig;
                const uint32_t b0 = *(const uint32_t*)(bp);
                const uint32_t b1 = *(const uint32_t*)(bp + 8);
                mma16816(c[0][j], a[0], b0, b1);
                mma16816(c[1][j], a[1], b0, b1);
            }
        }
        __syncthreads();
    }

    // epilogue: regs -> os[128][132] (+bias) -> coalesced STG.128
#pragma unroll
    for (int i = 0; i < 2; i++) {
#pragma unroll
        for (int j = 0; j < 8; j++) {
            const int r  = wm * 32 + i * 16 + gid;
            const int cb = wn * 64 + j * 8 + 2 * tig;
            const float2 bb = *(const float2*)(bias + n0 + cb);
            *(float2*)(os + r * 132 + cb) =
                make_float2(c[i][j][0] + bb.x, c[i][j][1] + bb.y);
            *(float2*)(os + (r + 8) * 132 + cb) =
                make_float2(c[i][j][2] + bb.x, c[i][j][3] + bb.y);
        }
    }
    __syncthreads();
    for (int i = tid; i < 128 * 32; i += 256) {
        const int r  = i >> 5;
        const int c4 = i & 31;
        *(float4*)(out + (size_t)(m0 + r) * G3 + n0 + 4 * c4) =
            *(const float4*)(os + r * 132 + 4 * c4);
    }
}

// ---------------------------------------------------------------------------
// GRU recurrence (R6 structure, calibrated near its RF-banking floor).
// 128 blocks x 4 batches, 384 threads. Layer 1 emits h1 as bf16 hi/lo.
// ---------------------------------------------------------------------------
template<bool LAYER1>
__global__ __launch_bounds__(384, 1)
void gru_recur(const float* __restrict__ Whh, const float* __restrict__ bhh,
               const float* __restrict__ gi,
               __nv_bfloat16* __restrict__ h1hi, __nv_bfloat16* __restrict__ h1lo,
               const float* __restrict__ Wfc, const float* __restrict__ bfc,
               float* __restrict__ out)
{
    __shared__ float h_s[64 * 8];        // [k2][b][2]
    __shared__ float gh_s[4 * 384];      // kh=0 partial (+ bias)
    __shared__ float ph_s[4 * 384];      // kh=1 partial
    __shared__ float gi_s[2 * 4 * 384];  // double-buffered

    const int tid = threadIdx.x;
    const int j2  = tid % 192;
    const int kh  = tid / 192;           // uniform per warp
    const int c0  = j2;
    const int c1  = j2 + 192;
    const int b0  = blockIdx.x * 4;

    unsigned long long w2a[32], w2b[32];
    {
        const ulonglong2* wp0 = (const ulonglong2*)(Whh + (size_t)c0 * H_DIM + kh * 64);
        const ulonglong2* wp1 = (const ulonglong2*)(Whh + (size_t)c1 * H_DIM + kh * 64);
#pragma unroll
        for (int q = 0; q < 16; q++) {
            ulonglong2 v0 = wp0[q];
            w2a[2 * q] = v0.x; w2a[2 * q + 1] = v0.y;
            ulonglong2 v1 = wp1[q];
            w2b[2 * q] = v1.x; w2b[2 * q + 1] = v1.y;
        }
    }
    const float bh0 = bhh[c0];
    const float bh1 = bhh[c1];

    for (int i = tid; i < 512; i += 384) h_s[i] = 0.0f;
#pragma unroll
    for (int b = 0; b < 4; b++)
        gi_s[b * 384 + tid] = gi[((size_t)(b0 + b) * T_SEQ) * G3 + tid];
    __syncthreads();

    const int k2base = kh * 32;

    for (int t = 0; t < T_SEQ; t++) {
        float* gin = gi_s + (t & 1) * 1536;
        float* gip = gi_s + ((t + 1) & 1) * 1536;

        float gv0 = 0.f, gv1 = 0.f, gv2 = 0.f, gv3 = 0.f;
        const bool pf = (t + 1 < T_SEQ);
        if (pf) {
            const float* gb = gi + ((size_t)b0 * T_SEQ + (t + 1)) * G3 + tid;
            gv0 = gb[0];
            gv1 = gb[(size_t)T_SEQ * G3];
            gv2 = gb[(size_t)2 * T_SEQ * G3];
            gv3 = gb[(size_t)3 * T_SEQ * G3];
        }

        unsigned long long a00 = 0, a01 = 0, a02 = 0, a03 = 0;
        unsigned long long a10 = 0, a11 = 0, a12 = 0, a13 = 0;
        const float* hp = h_s + k2base * 8;
#pragma unroll
        for (int q = 0; q < 32; q++) {
            const ulonglong2 h01 = *(const ulonglong2*)(hp + q * 8);
            const ulonglong2 h23 = *(const ulonglong2*)(hp + q * 8 + 4);
            const unsigned long long wd0 = w2a[q];
            const unsigned long long wd1 = w2b[q];
            a00 = ffma2(wd0, h01.x, a00);
            a01 = ffma2(wd0, h01.y, a01);
            a02 = ffma2(wd0, h23.x, a02);
            a03 = ffma2(wd0, h23.y, a03);
            a10 = ffma2(wd1, h01.x, a10);
            a11 = ffma2(wd1, h01.y, a11);
            a12 = ffma2(wd1, h23.x, a12);
            a13 = ffma2(wd1, h23.y, a13);
        }
        {
            float lo, hi;
            float* dst = kh ? ph_s : gh_s;
            const float add0 = kh ? 0.0f : bh0;
            const float add1 = kh ? 0.0f : bh1;
            unpack2(a00, lo, hi); dst[c0]           = add0 + lo + hi;
            unpack2(a01, lo, hi); dst[384 + c0]     = add0 + lo + hi;
            unpack2(a02, lo, hi); dst[2 * 384 + c0] = add0 + lo + hi;
            unpack2(a03, lo, hi); dst[3 * 384 + c0] = add0 + lo + hi;
            unpack2(a10, lo, hi); dst[c1]           = add1 + lo + hi;
            unpack2(a11, lo, hi); dst[384 + c1]     = add1 + lo + hi;
            unpack2(a12, lo, hi); dst[2 * 384 + c1] = add1 + lo + hi;
            unpack2(a13, lo, hi); dst[3 * 384 + c1] = add1 + lo + hi;
        }
        __syncthreads();

        for (int i = tid; i < 512; i += 384) {
            const int b  = i >> 7;
            const int jh = i & 127;
            const float* gib = gin + b * 384;
            const float* ghb = gh_s + b * 384;
            const float* phb = ph_s + b * 384;
            const float hr = ghb[jh]       + phb[jh];
            const float hz = ghb[jh + 128] + phb[jh + 128];
            const float hn = ghb[jh + 256] + phb[jh + 256];
            const float r = sigf(gib[jh]       + hr);
            const float z = sigf(gib[jh + 128] + hz);
            const float n = tanhfast(gib[jh + 256] + r * hn);
            const int hidx = (jh >> 1) * 8 + 2 * b + (jh & 1);
            const float ho = h_s[hidx];
            const float hv = n + z * (ho - n);
            h_s[hidx] = hv;
            if (LAYER1) {
                const size_t oidx = ((size_t)(b0 + b) * T_SEQ + t) * H_DIM + jh;
                const __nv_bfloat16 hh = __float2bfloat16(hv);
                h1hi[oidx] = hh;
                h1lo[oidx] = __float2bfloat16(hv - __bfloat162float(hh));
            }
        }
        if (pf) {
            gip[tid]           = gv0;
            gip[384 + tid]     = gv1;
            gip[2 * 384 + tid] = gv2;
            gip[3 * 384 + tid] = gv3;
        }
        __syncthreads();
    }

    if (!LAYER1) {
        if (tid < 128) {
            const int w = tid >> 5;
            const int l = tid & 31;
            float s = 0.0f;
#pragma unroll
            for (int q = 0; q < 4; q++) {
                const int jh = l + 32 * q;
                s += h_s[(jh >> 1) * 8 + 2 * w + (jh & 1)] * Wfc[jh];
            }
#pragma unroll
            for (int off = 16; off; off >>= 1)
                s += __shfl_down_sync(0xffffffffu, s, off);
            if (l == 0) out[b0 + w] = s + bfc[0];
        }
    }
}

// ---------------------------------------------------------------------------
extern "C" void kernel_launch(void* const* d_in, const int* in_sizes, int n_in,
                              void* d_out, int out_size)
{
    const float* x     = (const float*)d_in[0];
    const float* W_ih0 = (const float*)d_in[1];
    const float* W_hh0 = (const float*)d_in[2];
    const float* b_ih0 = (const float*)d_in[3];
    const float* b_hh0 = (const float*)d_in[4];
    const float* W_ih1 = (const float*)d_in[5];
    const float* W_hh1 = (const float*)d_in[6];
    const float* b_ih1 = (const float*)d_in[7];
    const float* b_hh1 = (const float*)d_in[8];
    const float* W_fc  = (const float*)d_in[9];
    const float* b_fc  = (const float*)d_in[10];
    float* out = (float*)d_out;

    void *p;
    cudaGetSymbolAddress(&p, g_gi);   float* gi = (float*)p;
    cudaGetSymbolAddress(&p, g_xhi);  __nv_bfloat16* xhi = (__nv_bfloat16*)p;
    cudaGetSymbolAddress(&p, g_xlo);  __nv_bfloat16* xlo = (__nv_bfloat16*)p;
    cudaGetSymbolAddress(&p, g_h1hi); __nv_bfloat16* h1hi = (__nv_bfloat16*)p;
    cudaGetSymbolAddress(&p, g_h1lo); __nv_bfloat16* h1lo = (__nv_bfloat16*)p;
    cudaGetSymbolAddress(&p, g_w0hi); __nv_bfloat16* w0hi = (__nv_bfloat16*)p;
    cudaGetSymbolAddress(&p, g_w0lo); __nv_bfloat16* w0lo = (__nv_bfloat16*)p;
    cudaGetSymbolAddress(&p, g_w1hi); __nv_bfloat16* w1hi = (__nv_bfloat16*)p;
    cudaGetSymbolAddress(&p, g_w1lo); __nv_bfloat16* w1lo = (__nv_bfloat16*)p;

    cudaFuncSetAttribute(gemm_mma<64>,  cudaFuncAttributeMaxDynamicSharedMemorySize, GEMM_SMEM);
    cudaFuncSetAttribute(gemm_mma<128>, cudaFuncAttributeMaxDynamicSharedMemorySize, GEMM_SMEM);

    // splits (x is 16.8M elems; W splits tiny)
    split_hilo<<<2048, 256>>>(x, xhi, xlo, M_TOT * 64);
    split_hilo<<<48, 256>>>(W_ih0, w0hi, w0lo, G3 * 64);
    split_hilo<<<96, 256>>>(W_ih1, w1hi, w1lo, G3 * 128);

    dim3 ggrid(M_TOT / 128, 3);
    // layer 1
    gemm_mma<64><<<ggrid, 256, GEMM_SMEM>>>(xhi, xlo, w0hi, w0lo, b_ih0, gi);
    gru_recur<true><<<128, 384>>>(W_hh0, b_hh0, gi, h1hi, h1lo,
                                  nullptr, nullptr, nullptr);
    // layer 2
    gemm_mma<128><<<ggrid, 256, GEMM_SMEM>>>(h1hi, h1lo, w1hi, w1lo, b_ih1, gi);
    gru_recur<false><<<128, 384>>>(W_hh1, b_hh1, gi, nullptr, nullptr,
                                   W_fc, b_fc, out);
}